// round 1
// baseline (speedup 1.0000x reference)
#include <cuda_runtime.h>
#include <math.h>

#define B_ 8
#define N_ 1024
#define HID_ 1024
#define HEADS_ 16
#define HD_ 64
#define GDIM_ 128

// Scratch (allocation-free rule: __device__ globals)
__device__ float g_Q[B_ * N_ * HID_];
__device__ float g_K[B_ * N_ * HID_];
__device__ float g_V[B_ * N_ * HID_];
__device__ float g_O[B_ * N_ * HID_];
__device__ float g_addk[B_ * HID_];

// ---------------------------------------------------------------------------
// Prep: addk[b][c] = elu(gc[b] @ Wgk + bgk)[c] + ct_key_emb[ct[b]][c]
// ---------------------------------------------------------------------------
__global__ void prep_addk_kernel(const int* __restrict__ ct,
                                 const float* __restrict__ gc,
                                 const float* __restrict__ Wgk,
                                 const float* __restrict__ bgk,
                                 const float* __restrict__ ct_key_emb) {
    int b = blockIdx.x;
    int tid = threadIdx.x;  // 128 threads
    __shared__ float g[GDIM_];
    g[tid] = gc[b * GDIM_ + tid];
    __syncthreads();
    int ctb = ct[b];
    for (int c = tid; c < HID_; c += GDIM_) {
        float s = bgk[c];
        #pragma unroll 8
        for (int i = 0; i < GDIM_; i++) s = fmaf(g[i], Wgk[i * HID_ + c], s);
        float e = (s > 0.f) ? s : (expf(s) - 1.f);
        g_addk[b * HID_ + c] = e + ct_key_emb[ctb * HID_ + c];
    }
}

// ---------------------------------------------------------------------------
// SGEMM: C[M,1024] = A[M,1024] @ W[1024,1024] + bias (+ per-batch addk)
// 128x128 block tile, BK=8, 256 threads, 8x8 microtile
// ---------------------------------------------------------------------------
__global__ __launch_bounds__(256) void sgemm_bias_kernel(
    const float* __restrict__ A, const float* __restrict__ W,
    const float* __restrict__ bias, const float* __restrict__ addk,
    float* __restrict__ C) {
    const int K = 1024, NN = 1024;
    __shared__ float As[8][128];
    __shared__ float Bs[8][132];

    int tid = threadIdx.x;
    int m0 = blockIdx.y * 128;
    int n0 = blockIdx.x * 128;
    int tx = tid & 15, ty = tid >> 4;

    int arow = tid >> 1, akk = (tid & 1) * 4;
    int brow = tid >> 5, bcol = (tid & 31) * 4;

    float acc[8][8];
    #pragma unroll
    for (int i = 0; i < 8; i++)
        #pragma unroll
        for (int j = 0; j < 8; j++) acc[i][j] = 0.f;

    for (int k0 = 0; k0 < K; k0 += 8) {
        float4 a4 = *(const float4*)(A + (size_t)(m0 + arow) * K + k0 + akk);
        As[akk + 0][arow] = a4.x;
        As[akk + 1][arow] = a4.y;
        As[akk + 2][arow] = a4.z;
        As[akk + 3][arow] = a4.w;
        *(float4*)&Bs[brow][bcol] =
            *(const float4*)(W + (size_t)(k0 + brow) * NN + n0 + bcol);
        __syncthreads();
        #pragma unroll
        for (int k = 0; k < 8; k++) {
            float4 a0 = *(float4*)&As[k][ty * 8];
            float4 a1 = *(float4*)&As[k][ty * 8 + 4];
            float4 b0 = *(float4*)&Bs[k][tx * 8];
            float4 b1 = *(float4*)&Bs[k][tx * 8 + 4];
            float ar[8] = {a0.x, a0.y, a0.z, a0.w, a1.x, a1.y, a1.z, a1.w};
            float br[8] = {b0.x, b0.y, b0.z, b0.w, b1.x, b1.y, b1.z, b1.w};
            #pragma unroll
            for (int i = 0; i < 8; i++)
                #pragma unroll
                for (int j = 0; j < 8; j++)
                    acc[i][j] = fmaf(ar[i], br[j], acc[i][j]);
        }
        __syncthreads();
    }

    int b = m0 >> 10;  // 128-row tiles never straddle a 1024-row batch
    #pragma unroll
    for (int i = 0; i < 8; i++) {
        int row = m0 + ty * 8 + i;
        float* crow = C + (size_t)row * NN + n0 + tx * 8;
        #pragma unroll
        for (int j = 0; j < 8; j++) {
            int col = n0 + tx * 8 + j;
            float bb = bias[col];
            if (addk) bb += addk[b * HID_ + col];
            acc[i][j] += bb;
        }
        *(float4*)crow = make_float4(acc[i][0], acc[i][1], acc[i][2], acc[i][3]);
        *(float4*)(crow + 4) = make_float4(acc[i][4], acc[i][5], acc[i][6], acc[i][7]);
    }
}

// ---------------------------------------------------------------------------
// Flash attention: one block = (b, h, 64-row q tile). 64x64 k tiles.
// Per-(b,h) scalar bias cancels in softmax -> omitted. Q prescaled by 1/8.
// ---------------------------------------------------------------------------
#define TPAD 68
#define ATTN_SMEM (4 * 64 * TPAD * (int)sizeof(float))

__global__ __launch_bounds__(256) void attn_kernel(
    const float* __restrict__ Q, const float* __restrict__ K,
    const float* __restrict__ V, const unsigned char* __restrict__ mask,
    float* __restrict__ O) {
    extern __shared__ float sm[];
    float* Qs = sm;
    float* Ks = Qs + 64 * TPAD;
    float* Vs = Ks + 64 * TPAD;
    float* Ps = Vs + 64 * TPAD;
    __shared__ unsigned char Ms[64];

    int tid = threadIdx.x;
    int qt = blockIdx.x, h = blockIdx.y, b = blockIdx.z;
    int tx = tid & 15, ty = tid >> 4;

    const float inv_scale = 0.125f;  // 1/sqrt(64)

    const float* Qbase = Q + ((size_t)(b * N_ + qt * 64) * HID_ + h * HD_);
    #pragma unroll
    for (int it = 0; it < 4; it++) {
        int i = tid + it * 256;  // 1024 float4 slots: 64 rows x 16
        int r = i >> 4, d4 = i & 15;
        float4 q4 = *(const float4*)(Qbase + (size_t)r * HID_ + d4 * 4);
        q4.x *= inv_scale; q4.y *= inv_scale; q4.z *= inv_scale; q4.w *= inv_scale;
        *(float4*)&Qs[r * TPAD + d4 * 4] = q4;
    }

    float m_i[4], l_i[4], o[4][4];
    #pragma unroll
    for (int i = 0; i < 4; i++) {
        m_i[i] = -INFINITY;
        l_i[i] = 0.f;
        #pragma unroll
        for (int j = 0; j < 4; j++) o[i][j] = 0.f;
    }

    for (int kt = 0; kt < 16; kt++) {
        const float* Kbase = K + ((size_t)(b * N_ + kt * 64) * HID_ + h * HD_);
        const float* Vbase = V + ((size_t)(b * N_ + kt * 64) * HID_ + h * HD_);
        __syncthreads();  // prior PV done before overwriting Ks/Vs; also covers Qs on kt=0
        #pragma unroll
        for (int it = 0; it < 4; it++) {
            int i = tid + it * 256;
            int r = i >> 4, d4 = i & 15;
            *(float4*)&Ks[r * TPAD + d4 * 4] =
                *(const float4*)(Kbase + (size_t)r * HID_ + d4 * 4);
            *(float4*)&Vs[r * TPAD + d4 * 4] =
                *(const float4*)(Vbase + (size_t)r * HID_ + d4 * 4);
        }
        if (tid < 64) Ms[tid] = mask[b * N_ + kt * 64 + tid];
        __syncthreads();

        // S = (Q/scale) K^T
        float s[4][4];
        #pragma unroll
        for (int i = 0; i < 4; i++)
            #pragma unroll
            for (int j = 0; j < 4; j++) s[i][j] = 0.f;
        #pragma unroll
        for (int d = 0; d < 64; d += 4) {
            float4 q[4], kk[4];
            #pragma unroll
            for (int i = 0; i < 4; i++) q[i] = *(float4*)&Qs[(ty * 4 + i) * TPAD + d];
            #pragma unroll
            for (int j = 0; j < 4; j++) kk[j] = *(float4*)&Ks[(tx * 4 + j) * TPAD + d];
            #pragma unroll
            for (int i = 0; i < 4; i++)
                #pragma unroll
                for (int j = 0; j < 4; j++) {
                    s[i][j] = fmaf(q[i].x, kk[j].x, s[i][j]);
                    s[i][j] = fmaf(q[i].y, kk[j].y, s[i][j]);
                    s[i][j] = fmaf(q[i].z, kk[j].z, s[i][j]);
                    s[i][j] = fmaf(q[i].w, kk[j].w, s[i][j]);
                }
        }
        #pragma unroll
        for (int j = 0; j < 4; j++)
            if (Ms[tx * 4 + j]) {
                #pragma unroll
                for (int i = 0; i < 4; i++) s[i][j] = -INFINITY;
            }

        // online softmax; each row owned by the 16 lanes sharing ty
        #pragma unroll
        for (int i = 0; i < 4; i++) {
            float rm = fmaxf(fmaxf(s[i][0], s[i][1]), fmaxf(s[i][2], s[i][3]));
            #pragma unroll
            for (int off = 8; off; off >>= 1)
                rm = fmaxf(rm, __shfl_xor_sync(0xffffffffu, rm, off));
            float nm = fmaxf(m_i[i], rm);
            float alpha = __expf(m_i[i] - nm);
            float ps = 0.f;
            #pragma unroll
            for (int j = 0; j < 4; j++) {
                float p = __expf(s[i][j] - nm);
                s[i][j] = p;
                ps += p;
            }
            #pragma unroll
            for (int off = 8; off; off >>= 1)
                ps += __shfl_xor_sync(0xffffffffu, ps, off);
            l_i[i] = l_i[i] * alpha + ps;
            m_i[i] = nm;
            #pragma unroll
            for (int j = 0; j < 4; j++) o[i][j] *= alpha;
        }
        #pragma unroll
        for (int i = 0; i < 4; i++)
            *(float4*)&Ps[(ty * 4 + i) * TPAD + tx * 4] =
                make_float4(s[i][0], s[i][1], s[i][2], s[i][3]);
        __syncthreads();

        // O += P V
        #pragma unroll 4
        for (int c = 0; c < 64; c++) {
            float4 v4 = *(float4*)&Vs[c * TPAD + tx * 4];
            #pragma unroll
            for (int i = 0; i < 4; i++) {
                float p = Ps[(ty * 4 + i) * TPAD + c];
                o[i][0] = fmaf(p, v4.x, o[i][0]);
                o[i][1] = fmaf(p, v4.y, o[i][1]);
                o[i][2] = fmaf(p, v4.z, o[i][2]);
                o[i][3] = fmaf(p, v4.w, o[i][3]);
            }
        }
    }

    #pragma unroll
    for (int i = 0; i < 4; i++) {
        float inv_l = 1.f / l_i[i];
        int q = qt * 64 + ty * 4 + i;
        float* orow = O + ((size_t)(b * N_ + q) * HID_ + h * HD_ + tx * 4);
        *(float4*)orow = make_float4(o[i][0] * inv_l, o[i][1] * inv_l,
                                     o[i][2] * inv_l, o[i][3] * inv_l);
    }
}

// ---------------------------------------------------------------------------
extern "C" void kernel_launch(void* const* d_in, const int* in_sizes, int n_in,
                              void* d_out, int out_size) {
    const float* x = (const float*)d_in[0];
    const int* ct = (const int*)d_in[1];
    const float* gc = (const float*)d_in[2];
    const unsigned char* mask = (const unsigned char*)d_in[3];
    const float* Wq = (const float*)d_in[4];
    const float* bq = (const float*)d_in[5];
    const float* Wk = (const float*)d_in[6];
    const float* bk = (const float*)d_in[7];
    const float* Wv = (const float*)d_in[8];
    const float* bv = (const float*)d_in[9];
    const float* Wo = (const float*)d_in[10];
    const float* bo = (const float*)d_in[11];
    // d_in[12] ct_bias_emb, d_in[14..17] Wg1/bg1/Wg2/bg2: cancel in softmax
    const float* ct_key = (const float*)d_in[13];
    const float* Wgk = (const float*)d_in[18];
    const float* bgk = (const float*)d_in[19];

    float *Qb, *Kb, *Vb, *Ob, *addk;
    cudaGetSymbolAddress((void**)&Qb, g_Q);
    cudaGetSymbolAddress((void**)&Kb, g_K);
    cudaGetSymbolAddress((void**)&Vb, g_V);
    cudaGetSymbolAddress((void**)&Ob, g_O);
    cudaGetSymbolAddress((void**)&addk, g_addk);

    cudaFuncSetAttribute(attn_kernel, cudaFuncAttributeMaxDynamicSharedMemorySize,
                         ATTN_SMEM);

    prep_addk_kernel<<<B_, GDIM_>>>(ct, gc, Wgk, bgk, ct_key);

    dim3 gblock(256);
    dim3 ggrid(HID_ / 128, (B_ * N_) / 128);  // (8, 64)
    sgemm_bias_kernel<<<ggrid, gblock>>>(x, Wq, bq, nullptr, Qb);
    sgemm_bias_kernel<<<ggrid, gblock>>>(x, Wk, bk, addk, Kb);
    sgemm_bias_kernel<<<ggrid, gblock>>>(x, Wv, bv, nullptr, Vb);

    dim3 agrid(N_ / 64, HEADS_, B_);  // (16, 16, 8)
    attn_kernel<<<agrid, 256, ATTN_SMEM>>>(Qb, Kb, Vb, mask, Ob);

    sgemm_bias_kernel<<<ggrid, gblock>>>(Ob, Wo, bo, nullptr, (float*)d_out);
}